// round 4
// baseline (speedup 1.0000x reference)
#include <cuda_runtime.h>
#include <cuda_bf16.h>
#include <cstdint>

// RNNModel: T=512, B=256, I=256, H=512, fp32.
//   K1: xp = x @ w_ih^T + (b_ih + b_hh)      -> f32x2 FFMA GEMM (proven)
//   K2: h_t = tanh(xp_t + h_{t-1} @ w_hh^T)  -> persistent kernel, CLUSTER-barrier sync
//   K3: out = hs @ w_fc^T + b_fc             -> f32x2 FFMA GEMM (proven)
// NOTE: tcgen05 is unavailable (harness ptxas target is compute_103, not 103a).

#define T_ 512
#define B_ 256
#define I_ 256
#define H_ 512

#define NG  16   // batch groups == clusters
#define NSL 8    // H slices per group == cluster size
#define BT  16   // batch rows per group
#define NS  64   // H cols per slice
#define WPAD 68

__device__ float g_xp[(size_t)T_ * B_ * H_];
__device__ float g_hs[(size_t)T_ * B_ * H_];

// ---------------- f32x2 helpers ----------------
__device__ __forceinline__ unsigned long long f32x2_fma(unsigned long long a,
                                                        unsigned long long b,
                                                        unsigned long long c) {
    unsigned long long d;
    asm("fma.rn.f32x2 %0, %1, %2, %3;" : "=l"(d) : "l"(a), "l"(b), "l"(c));
    return d;
}
__device__ __forceinline__ unsigned long long f32x2_splat(float x) {
    unsigned long long d;
    unsigned int xi = __float_as_uint(x);
    asm("mov.b64 %0, {%1, %1};" : "=l"(d) : "r"(xi));
    return d;
}
__device__ __forceinline__ float2 f32x2_unpack(unsigned long long v) {
    unsigned int lo, hi;
    asm("mov.b64 {%0, %1}, %2;" : "=r"(lo), "=r"(hi) : "l"(v));
    float2 r;
    r.x = __uint_as_float(lo);
    r.y = __uint_as_float(hi);
    return r;
}

// ---------------- K1/K3: C[M,N] = A[M,K] * B[N,K]^T + b1[n] (+b2[n]) ----------------
__global__ void __launch_bounds__(256) sgemm_bias_kernel(
    const float* __restrict__ A, const float* __restrict__ Bm,
    const float* __restrict__ b1, const float* __restrict__ b2,
    float* __restrict__ C, int M, int N, int K)
{
    __shared__ __align__(16) float As[8 * 128];
    __shared__ __align__(16) float Bs[8 * 128];

    const int tid = threadIdx.x;
    const int m0 = blockIdx.y * 128;
    const int n0 = blockIdx.x * 128;

    const int lr = tid >> 1;
    const int lc = (tid & 1) << 2;
    const float* Ap = A + (size_t)(m0 + lr) * K + lc;
    const float* Bp = Bm + (size_t)(n0 + lr) * K + lc;

    const int tx = tid & 15;
    const int ty = tid >> 4;

    unsigned long long acc[8][4];
#pragma unroll
    for (int i = 0; i < 8; i++)
#pragma unroll
        for (int j = 0; j < 4; j++) acc[i][j] = 0ull;

    float4 av = *(const float4*)Ap;
    float4 bv = *(const float4*)Bp;

    for (int kt = 0; kt < K; kt += 8) {
        As[(lc + 0) * 128 + lr] = av.x;
        As[(lc + 1) * 128 + lr] = av.y;
        As[(lc + 2) * 128 + lr] = av.z;
        As[(lc + 3) * 128 + lr] = av.w;
        Bs[(lc + 0) * 128 + lr] = bv.x;
        Bs[(lc + 1) * 128 + lr] = bv.y;
        Bs[(lc + 2) * 128 + lr] = bv.z;
        Bs[(lc + 3) * 128 + lr] = bv.w;
        __syncthreads();

        if (kt + 8 < K) {
            av = *(const float4*)(Ap + kt + 8);
            bv = *(const float4*)(Bp + kt + 8);
        }

#pragma unroll
        for (int k = 0; k < 8; k++) {
            float4 a0 = *(const float4*)&As[k * 128 + ty * 8];
            float4 a1 = *(const float4*)&As[k * 128 + ty * 8 + 4];
            ulonglong2 w0 = *(const ulonglong2*)&Bs[k * 128 + tx * 8];
            ulonglong2 w1 = *(const ulonglong2*)&Bs[k * 128 + tx * 8 + 4];
            float aarr[8] = {a0.x, a0.y, a0.z, a0.w, a1.x, a1.y, a1.z, a1.w};
            unsigned long long wv[4] = {w0.x, w0.y, w1.x, w1.y};
#pragma unroll
            for (int i = 0; i < 8; i++) {
                unsigned long long s = f32x2_splat(aarr[i]);
#pragma unroll
                for (int j = 0; j < 4; j++)
                    acc[i][j] = f32x2_fma(s, wv[j], acc[i][j]);
            }
        }
        __syncthreads();
    }

    float bias[8];
#pragma unroll
    for (int j = 0; j < 8; j++) {
        int col = n0 + tx * 8 + j;
        float bb = b1[col];
        if (b2) bb += b2[col];
        bias[j] = bb;
    }
#pragma unroll
    for (int i = 0; i < 8; i++) {
        float o[8];
#pragma unroll
        for (int j = 0; j < 4; j++) {
            float2 v = f32x2_unpack(acc[i][j]);
            o[2 * j + 0] = v.x + bias[2 * j + 0];
            o[2 * j + 1] = v.y + bias[2 * j + 1];
        }
        float4* cp = (float4*)&C[(size_t)(m0 + ty * 8 + i) * N + n0 + tx * 8];
        cp[0] = make_float4(o[0], o[1], o[2], o[3]);
        cp[1] = make_float4(o[4], o[5], o[6], o[7]);
    }
}

// ---------------- K2: persistent recurrence with CLUSTER sync ----------------
// 16 clusters x 8 CTAs. Cluster = batch group (16 rows); CTA rank = H slice (64 cols).
// Per step: compute slice -> STG h slice -> barrier.cluster (release/acquire) -> ldcg h.
__global__ void __launch_bounds__(256) __cluster_dims__(NSL, 1, 1)
rnn_rec_kernel(const float* __restrict__ w_hh)
{
    extern __shared__ float sm[];
    float* w_t  = sm;                 // [H_][WPAD]
    float* hT   = sm + H_ * WPAD;     // [H_][BT] k-major h tile
    float* part = hT + H_ * BT;       // [8][BT*NS]

    const int tid = threadIdx.x;
    const int g = blockIdx.x >> 3;    // cluster index (batch group)
    const int s = blockIdx.x & 7;     // rank in cluster (H slice)
    const int n0 = s * NS;
    const int b0 = g * BT;

    // cache W_hh slice (k-major, padded)
    for (int i = tid; i < NS * H_; i += 256) {
        int n = i >> 9;
        int k = i & (H_ - 1);
        w_t[k * WPAD + n] = w_hh[(size_t)(n0 + n) * H_ + k];
    }

    const int wid = tid >> 5, lane = tid & 31;
    const int bg = lane >> 3;
    const int ng = lane & 7;
    const int k0 = wid * 64;

    __syncthreads();

    for (int t = 0; t < T_; t++) {
        // --- acquire h_{t-1}: cluster barrier at end of prev step guarantees visibility ---
        if (t > 0) {
            const float* hsrc = g_hs + ((size_t)(t - 1) * B_ + b0) * H_;
            for (int i = tid; i < BT * H_; i += 256) {
                int b = i >> 9;
                int k = i & (H_ - 1);
                hT[k * BT + b] = __ldcg(hsrc + i);   // L2 (bypass L1; peers wrote it)
            }
        } else {
            for (int i = tid; i < BT * H_; i += 256) hT[i] = 0.0f;
        }
        __syncthreads();

        // --- compute partial c[16][64] for this warp's K chunk ---
        unsigned long long acc[4][4];
#pragma unroll
        for (int b = 0; b < 4; b++)
#pragma unroll
            for (int j = 0; j < 4; j++) acc[b][j] = 0ull;

#pragma unroll 4
        for (int kk = 0; kk < 64; kk++) {
            int k = k0 + kk;
            float4 hv = *(const float4*)&hT[k * BT + bg * 4];
            ulonglong2 w0 = *(const ulonglong2*)&w_t[k * WPAD + ng * 8];
            ulonglong2 w1 = *(const ulonglong2*)&w_t[k * WPAD + ng * 8 + 4];
            float hh[4] = {hv.x, hv.y, hv.z, hv.w};
            unsigned long long wv[4] = {w0.x, w0.y, w1.x, w1.y};
#pragma unroll
            for (int b = 0; b < 4; b++) {
                unsigned long long hs2 = f32x2_splat(hh[b]);
#pragma unroll
                for (int j = 0; j < 4; j++)
                    acc[b][j] = f32x2_fma(hs2, wv[j], acc[b][j]);
            }
        }

        // --- write warp partials to smem ---
        {
            float* pw = part + wid * (BT * NS);
#pragma unroll
            for (int b = 0; b < 4; b++) {
                int r = (bg * 4 + b) * NS + ng * 8;
                ulonglong2 q0; q0.x = acc[b][0]; q0.y = acc[b][1];
                ulonglong2 q1; q1.x = acc[b][2]; q1.y = acc[b][3];
                *(ulonglong2*)&pw[r]     = q0;
                *(ulonglong2*)&pw[r + 4] = q1;
            }
        }
        __syncthreads();

        // --- reduce 8 warps, add xp, tanh, store h_t slice ---
        {
            int o = tid * 4;
            float4 sum = *(const float4*)&part[o];
#pragma unroll
            for (int ww = 1; ww < 8; ww++) {
                float4 p = *(const float4*)&part[ww * (BT * NS) + o];
                sum.x += p.x; sum.y += p.y; sum.z += p.z; sum.w += p.w;
            }
            int b = o >> 6;
            int n = o & (NS - 1);
            size_t gidx = ((size_t)t * B_ + b0 + b) * H_ + n0 + n;
            float4 xv = *(const float4*)&g_xp[gidx];
            float4 r;
            r.x = tanhf(sum.x + xv.x);
            r.y = tanhf(sum.y + xv.y);
            r.z = tanhf(sum.z + xv.z);
            r.w = tanhf(sum.w + xv.w);
            *(float4*)&g_hs[gidx] = r;
        }

        // --- release + acquire across the 8 slice-CTAs of this cluster ---
        asm volatile("barrier.cluster.arrive.aligned;" ::: "memory");
        asm volatile("barrier.cluster.wait.aligned;" ::: "memory");
    }
}

// ---------------- launch ----------------
extern "C" void kernel_launch(void* const* d_in, const int* in_sizes, int n_in,
                              void* d_out, int out_size)
{
    const float* x    = (const float*)d_in[0];
    const float* w_ih = (const float*)d_in[1];
    const float* w_hh = (const float*)d_in[2];
    const float* b_ih = (const float*)d_in[3];
    const float* b_hh = (const float*)d_in[4];
    const float* w_fc = (const float*)d_in[5];
    const float* b_fc = (const float*)d_in[6];
    float* out = (float*)d_out;

    float* xp = nullptr;
    float* hs = nullptr;
    cudaGetSymbolAddress((void**)&xp, g_xp);
    cudaGetSymbolAddress((void**)&hs, g_hs);

    const int rec_smem = (H_ * WPAD + H_ * BT + 8 * BT * NS) * (int)sizeof(float); // 204800
    cudaFuncSetAttribute(rnn_rec_kernel, cudaFuncAttributeMaxDynamicSharedMemorySize, rec_smem);

    const int M = T_ * B_;

    // K1: xp = x @ w_ih^T + (b_ih + b_hh)
    sgemm_bias_kernel<<<dim3(H_ / 128, M / 128), 256>>>(x, w_ih, b_ih, b_hh, xp, M, H_, I_);

    // K2: recurrence (persistent, 128 CTAs = 16 clusters x 8)
    rnn_rec_kernel<<<NG * NSL, 256, rec_smem>>>(w_hh);

    // K3: out = hs @ w_fc^T + b_fc
    sgemm_bias_kernel<<<dim3(I_ / 128, M / 128), 256>>>(hs, w_fc, b_fc, nullptr, out, M, I_, H_);
}

// round 5
// speedup vs baseline: 1.0014x; 1.0014x over previous
#include <cuda_runtime.h>
#include <cuda_bf16.h>
#include <cstdint>

// RNNModel: T=512, B=256, I=256, H=512, fp32.
//   K1: xp = x @ w_ih^T + (b_ih + b_hh)      -> f32x2 FFMA GEMM (proven)
//   K2: h_t = tanh(xp_t + h_{t-1} @ w_hh^T)  -> persistent kernel, CLUSTER-barrier sync
//   K3: out = hs @ w_fc^T + b_fc             -> f32x2 FFMA GEMM (proven)
// NOTE: tcgen05 is unavailable (harness ptxas target is compute_103, not 103a).

#define T_ 512
#define B_ 256
#define I_ 256
#define H_ 512

#define NG  16   // batch groups == clusters
#define NSL 8    // H slices per group == cluster size
#define BT  16   // batch rows per group
#define NS  64   // H cols per slice
#define WPAD 68

__device__ float g_xp[(size_t)T_ * B_ * H_];
__device__ float g_hs[(size_t)T_ * B_ * H_];

// ---------------- f32x2 helpers ----------------
__device__ __forceinline__ unsigned long long f32x2_fma(unsigned long long a,
                                                        unsigned long long b,
                                                        unsigned long long c) {
    unsigned long long d;
    asm("fma.rn.f32x2 %0, %1, %2, %3;" : "=l"(d) : "l"(a), "l"(b), "l"(c));
    return d;
}
__device__ __forceinline__ unsigned long long f32x2_splat(float x) {
    unsigned long long d;
    unsigned int xi = __float_as_uint(x);
    asm("mov.b64 %0, {%1, %1};" : "=l"(d) : "r"(xi));
    return d;
}
__device__ __forceinline__ float2 f32x2_unpack(unsigned long long v) {
    unsigned int lo, hi;
    asm("mov.b64 {%0, %1}, %2;" : "=r"(lo), "=r"(hi) : "l"(v));
    float2 r;
    r.x = __uint_as_float(lo);
    r.y = __uint_as_float(hi);
    return r;
}

// ---------------- K1/K3: C[M,N] = A[M,K] * B[N,K]^T + b1[n] (+b2[n]) ----------------
__global__ void __launch_bounds__(256) sgemm_bias_kernel(
    const float* __restrict__ A, const float* __restrict__ Bm,
    const float* __restrict__ b1, const float* __restrict__ b2,
    float* __restrict__ C, int M, int N, int K)
{
    __shared__ __align__(16) float As[8 * 128];
    __shared__ __align__(16) float Bs[8 * 128];

    const int tid = threadIdx.x;
    const int m0 = blockIdx.y * 128;
    const int n0 = blockIdx.x * 128;

    const int lr = tid >> 1;
    const int lc = (tid & 1) << 2;
    const float* Ap = A + (size_t)(m0 + lr) * K + lc;
    const float* Bp = Bm + (size_t)(n0 + lr) * K + lc;

    const int tx = tid & 15;
    const int ty = tid >> 4;

    unsigned long long acc[8][4];
#pragma unroll
    for (int i = 0; i < 8; i++)
#pragma unroll
        for (int j = 0; j < 4; j++) acc[i][j] = 0ull;

    float4 av = *(const float4*)Ap;
    float4 bv = *(const float4*)Bp;

    for (int kt = 0; kt < K; kt += 8) {
        As[(lc + 0) * 128 + lr] = av.x;
        As[(lc + 1) * 128 + lr] = av.y;
        As[(lc + 2) * 128 + lr] = av.z;
        As[(lc + 3) * 128 + lr] = av.w;
        Bs[(lc + 0) * 128 + lr] = bv.x;
        Bs[(lc + 1) * 128 + lr] = bv.y;
        Bs[(lc + 2) * 128 + lr] = bv.z;
        Bs[(lc + 3) * 128 + lr] = bv.w;
        __syncthreads();

        if (kt + 8 < K) {
            av = *(const float4*)(Ap + kt + 8);
            bv = *(const float4*)(Bp + kt + 8);
        }

#pragma unroll
        for (int k = 0; k < 8; k++) {
            float4 a0 = *(const float4*)&As[k * 128 + ty * 8];
            float4 a1 = *(const float4*)&As[k * 128 + ty * 8 + 4];
            ulonglong2 w0 = *(const ulonglong2*)&Bs[k * 128 + tx * 8];
            ulonglong2 w1 = *(const ulonglong2*)&Bs[k * 128 + tx * 8 + 4];
            float aarr[8] = {a0.x, a0.y, a0.z, a0.w, a1.x, a1.y, a1.z, a1.w};
            unsigned long long wv[4] = {w0.x, w0.y, w1.x, w1.y};
#pragma unroll
            for (int i = 0; i < 8; i++) {
                unsigned long long s = f32x2_splat(aarr[i]);
#pragma unroll
                for (int j = 0; j < 4; j++)
                    acc[i][j] = f32x2_fma(s, wv[j], acc[i][j]);
            }
        }
        __syncthreads();
    }

    float bias[8];
#pragma unroll
    for (int j = 0; j < 8; j++) {
        int col = n0 + tx * 8 + j;
        float bb = b1[col];
        if (b2) bb += b2[col];
        bias[j] = bb;
    }
#pragma unroll
    for (int i = 0; i < 8; i++) {
        float o[8];
#pragma unroll
        for (int j = 0; j < 4; j++) {
            float2 v = f32x2_unpack(acc[i][j]);
            o[2 * j + 0] = v.x + bias[2 * j + 0];
            o[2 * j + 1] = v.y + bias[2 * j + 1];
        }
        float4* cp = (float4*)&C[(size_t)(m0 + ty * 8 + i) * N + n0 + tx * 8];
        cp[0] = make_float4(o[0], o[1], o[2], o[3]);
        cp[1] = make_float4(o[4], o[5], o[6], o[7]);
    }
}

// ---------------- K2: persistent recurrence with CLUSTER sync ----------------
// 16 clusters x 8 CTAs. Cluster = batch group (16 rows); CTA rank = H slice (64 cols).
// Per step: compute slice -> STG h slice -> barrier.cluster (release/acquire) -> ldcg h.
__global__ void __launch_bounds__(256) __cluster_dims__(NSL, 1, 1)
rnn_rec_kernel(const float* __restrict__ w_hh)
{
    extern __shared__ float sm[];
    float* w_t  = sm;                 // [H_][WPAD]
    float* hT   = sm + H_ * WPAD;     // [H_][BT] k-major h tile
    float* part = hT + H_ * BT;       // [8][BT*NS]

    const int tid = threadIdx.x;
    const int g = blockIdx.x >> 3;    // cluster index (batch group)
    const int s = blockIdx.x & 7;     // rank in cluster (H slice)
    const int n0 = s * NS;
    const int b0 = g * BT;

    // cache W_hh slice (k-major, padded)
    for (int i = tid; i < NS * H_; i += 256) {
        int n = i >> 9;
        int k = i & (H_ - 1);
        w_t[k * WPAD + n] = w_hh[(size_t)(n0 + n) * H_ + k];
    }

    const int wid = tid >> 5, lane = tid & 31;
    const int bg = lane >> 3;
    const int ng = lane & 7;
    const int k0 = wid * 64;

    __syncthreads();

    for (int t = 0; t < T_; t++) {
        // --- acquire h_{t-1}: cluster barrier at end of prev step guarantees visibility ---
        if (t > 0) {
            const float* hsrc = g_hs + ((size_t)(t - 1) * B_ + b0) * H_;
            for (int i = tid; i < BT * H_; i += 256) {
                int b = i >> 9;
                int k = i & (H_ - 1);
                hT[k * BT + b] = __ldcg(hsrc + i);   // L2 (bypass L1; peers wrote it)
            }
        } else {
            for (int i = tid; i < BT * H_; i += 256) hT[i] = 0.0f;
        }
        __syncthreads();

        // --- compute partial c[16][64] for this warp's K chunk ---
        unsigned long long acc[4][4];
#pragma unroll
        for (int b = 0; b < 4; b++)
#pragma unroll
            for (int j = 0; j < 4; j++) acc[b][j] = 0ull;

#pragma unroll 4
        for (int kk = 0; kk < 64; kk++) {
            int k = k0 + kk;
            float4 hv = *(const float4*)&hT[k * BT + bg * 4];
            ulonglong2 w0 = *(const ulonglong2*)&w_t[k * WPAD + ng * 8];
            ulonglong2 w1 = *(const ulonglong2*)&w_t[k * WPAD + ng * 8 + 4];
            float hh[4] = {hv.x, hv.y, hv.z, hv.w};
            unsigned long long wv[4] = {w0.x, w0.y, w1.x, w1.y};
#pragma unroll
            for (int b = 0; b < 4; b++) {
                unsigned long long hs2 = f32x2_splat(hh[b]);
#pragma unroll
                for (int j = 0; j < 4; j++)
                    acc[b][j] = f32x2_fma(hs2, wv[j], acc[b][j]);
            }
        }

        // --- write warp partials to smem ---
        {
            float* pw = part + wid * (BT * NS);
#pragma unroll
            for (int b = 0; b < 4; b++) {
                int r = (bg * 4 + b) * NS + ng * 8;
                ulonglong2 q0; q0.x = acc[b][0]; q0.y = acc[b][1];
                ulonglong2 q1; q1.x = acc[b][2]; q1.y = acc[b][3];
                *(ulonglong2*)&pw[r]     = q0;
                *(ulonglong2*)&pw[r + 4] = q1;
            }
        }
        __syncthreads();

        // --- reduce 8 warps, add xp, tanh, store h_t slice ---
        {
            int o = tid * 4;
            float4 sum = *(const float4*)&part[o];
#pragma unroll
            for (int ww = 1; ww < 8; ww++) {
                float4 p = *(const float4*)&part[ww * (BT * NS) + o];
                sum.x += p.x; sum.y += p.y; sum.z += p.z; sum.w += p.w;
            }
            int b = o >> 6;
            int n = o & (NS - 1);
            size_t gidx = ((size_t)t * B_ + b0 + b) * H_ + n0 + n;
            float4 xv = *(const float4*)&g_xp[gidx];
            float4 r;
            r.x = tanhf(sum.x + xv.x);
            r.y = tanhf(sum.y + xv.y);
            r.z = tanhf(sum.z + xv.z);
            r.w = tanhf(sum.w + xv.w);
            *(float4*)&g_hs[gidx] = r;
        }

        // --- release + acquire across the 8 slice-CTAs of this cluster ---
        asm volatile("barrier.cluster.arrive.aligned;" ::: "memory");
        asm volatile("barrier.cluster.wait.aligned;" ::: "memory");
    }
}

// ---------------- launch ----------------
extern "C" void kernel_launch(void* const* d_in, const int* in_sizes, int n_in,
                              void* d_out, int out_size)
{
    const float* x    = (const float*)d_in[0];
    const float* w_ih = (const float*)d_in[1];
    const float* w_hh = (const float*)d_in[2];
    const float* b_ih = (const float*)d_in[3];
    const float* b_hh = (const float*)d_in[4];
    const float* w_fc = (const float*)d_in[5];
    const float* b_fc = (const float*)d_in[6];
    float* out = (float*)d_out;

    float* xp = nullptr;
    float* hs = nullptr;
    cudaGetSymbolAddress((void**)&xp, g_xp);
    cudaGetSymbolAddress((void**)&hs, g_hs);

    const int rec_smem = (H_ * WPAD + H_ * BT + 8 * BT * NS) * (int)sizeof(float); // 204800
    cudaFuncSetAttribute(rnn_rec_kernel, cudaFuncAttributeMaxDynamicSharedMemorySize, rec_smem);

    const int M = T_ * B_;

    // K1: xp = x @ w_ih^T + (b_ih + b_hh)
    sgemm_bias_kernel<<<dim3(H_ / 128, M / 128), 256>>>(x, w_ih, b_ih, b_hh, xp, M, H_, I_);

    // K2: recurrence (persistent, 128 CTAs = 16 clusters x 8)
    rnn_rec_kernel<<<NG * NSL, 256, rec_smem>>>(w_hh);

    // K3: out = hs @ w_fc^T + b_fc
    sgemm_bias_kernel<<<dim3(I_ / 128, M / 128), 256>>>(hs, w_fc, b_fc, nullptr, out, M, I_, H_);
}

// round 6
// speedup vs baseline: 1.5034x; 1.5013x over previous
#include <cuda_runtime.h>
#include <cuda_bf16.h>
#include <cstdint>

// RNNModel: T=512, B=256, I=256, H=512, fp32.
//   K1: xp = x @ w_ih^T + (b_ih + b_hh)      -> f32x2 FFMA GEMM (proven, unchanged)
//   K2: h_t = tanh(xp_t + h_{t-1} @ w_hh^T)  -> persistent kernel, PER-SLICE flag sync
//   K3: out = hs @ w_fc^T + b_fc             -> f32x2 FFMA GEMM (proven, unchanged)
// tcgen05 unavailable (harness ptxas target is compute_103); cluster barriers proven slower.

#define T_ 512
#define B_ 256
#define I_ 256
#define H_ 512

#define NG  16   // batch groups
#define NSL 8    // H slices per group (== warps per CTA)
#define BT  16   // batch rows per group
#define NS  64   // H cols per slice
#define WPAD 68

__device__ float g_xp[(size_t)T_ * B_ * H_];
__device__ float g_hs[(size_t)T_ * B_ * H_];
__device__ unsigned int g_flag[NG * NSL];   // flag[g*8+s] = steps completed by CTA (g,s)

// ---------------- f32x2 helpers ----------------
__device__ __forceinline__ unsigned long long f32x2_fma(unsigned long long a,
                                                        unsigned long long b,
                                                        unsigned long long c) {
    unsigned long long d;
    asm("fma.rn.f32x2 %0, %1, %2, %3;" : "=l"(d) : "l"(a), "l"(b), "l"(c));
    return d;
}
__device__ __forceinline__ unsigned long long f32x2_splat(float x) {
    unsigned long long d;
    unsigned int xi = __float_as_uint(x);
    asm("mov.b64 %0, {%1, %1};" : "=l"(d) : "r"(xi));
    return d;
}
__device__ __forceinline__ float2 f32x2_unpack(unsigned long long v) {
    unsigned int lo, hi;
    asm("mov.b64 {%0, %1}, %2;" : "=r"(lo), "=r"(hi) : "l"(v));
    float2 r;
    r.x = __uint_as_float(lo);
    r.y = __uint_as_float(hi);
    return r;
}

// ---------------- K1/K3 GEMM (unchanged from R1) ----------------
__global__ void __launch_bounds__(256) sgemm_bias_kernel(
    const float* __restrict__ A, const float* __restrict__ Bm,
    const float* __restrict__ b1, const float* __restrict__ b2,
    float* __restrict__ C, int M, int N, int K)
{
    __shared__ __align__(16) float As[8 * 128];
    __shared__ __align__(16) float Bs[8 * 128];

    const int tid = threadIdx.x;
    const int m0 = blockIdx.y * 128;
    const int n0 = blockIdx.x * 128;

    const int lr = tid >> 1;
    const int lc = (tid & 1) << 2;
    const float* Ap = A + (size_t)(m0 + lr) * K + lc;
    const float* Bp = Bm + (size_t)(n0 + lr) * K + lc;

    const int tx = tid & 15;
    const int ty = tid >> 4;

    unsigned long long acc[8][4];
#pragma unroll
    for (int i = 0; i < 8; i++)
#pragma unroll
        for (int j = 0; j < 4; j++) acc[i][j] = 0ull;

    float4 av = *(const float4*)Ap;
    float4 bv = *(const float4*)Bp;

    for (int kt = 0; kt < K; kt += 8) {
        As[(lc + 0) * 128 + lr] = av.x;
        As[(lc + 1) * 128 + lr] = av.y;
        As[(lc + 2) * 128 + lr] = av.z;
        As[(lc + 3) * 128 + lr] = av.w;
        Bs[(lc + 0) * 128 + lr] = bv.x;
        Bs[(lc + 1) * 128 + lr] = bv.y;
        Bs[(lc + 2) * 128 + lr] = bv.z;
        Bs[(lc + 3) * 128 + lr] = bv.w;
        __syncthreads();

        if (kt + 8 < K) {
            av = *(const float4*)(Ap + kt + 8);
            bv = *(const float4*)(Bp + kt + 8);
        }

#pragma unroll
        for (int k = 0; k < 8; k++) {
            float4 a0 = *(const float4*)&As[k * 128 + ty * 8];
            float4 a1 = *(const float4*)&As[k * 128 + ty * 8 + 4];
            ulonglong2 w0 = *(const ulonglong2*)&Bs[k * 128 + tx * 8];
            ulonglong2 w1 = *(const ulonglong2*)&Bs[k * 128 + tx * 8 + 4];
            float aarr[8] = {a0.x, a0.y, a0.z, a0.w, a1.x, a1.y, a1.z, a1.w};
            unsigned long long wv[4] = {w0.x, w0.y, w1.x, w1.y};
#pragma unroll
            for (int i = 0; i < 8; i++) {
                unsigned long long s = f32x2_splat(aarr[i]);
#pragma unroll
                for (int j = 0; j < 4; j++)
                    acc[i][j] = f32x2_fma(s, wv[j], acc[i][j]);
            }
        }
        __syncthreads();
    }

    float bias[8];
#pragma unroll
    for (int j = 0; j < 8; j++) {
        int col = n0 + tx * 8 + j;
        float bb = b1[col];
        if (b2) bb += b2[col];
        bias[j] = bb;
    }
#pragma unroll
    for (int i = 0; i < 8; i++) {
        float o[8];
#pragma unroll
        for (int j = 0; j < 4; j++) {
            float2 v = f32x2_unpack(acc[i][j]);
            o[2 * j + 0] = v.x + bias[2 * j + 0];
            o[2 * j + 1] = v.y + bias[2 * j + 1];
        }
        float4* cp = (float4*)&C[(size_t)(m0 + ty * 8 + i) * N + n0 + tx * 8];
        cp[0] = make_float4(o[0], o[1], o[2], o[3]);
        cp[1] = make_float4(o[4], o[5], o[6], o[7]);
    }
}

// ---------------- init ----------------
__global__ void zero_flag_kernel() {
    if (threadIdx.x < NG * NSL) g_flag[threadIdx.x] = 0u;
}

// ---------------- K2: persistent recurrence, per-slice flags ----------------
// 128 CTAs = 16 groups x 8 slices, all co-resident (1/SM via 204.8KB smem).
// Warp w of CTA (g,s) consumes k-range [64w,64w+64) == the n-slice produced by CTA (g,w):
// it spins on flag[g][w] alone, loads its 4KB hT chunk, computes — producer skew
// overlaps with compute instead of summing at a group rendezvous.
__global__ void __launch_bounds__(256)
rnn_rec_kernel(const float* __restrict__ w_hh)
{
    extern __shared__ float sm[];
    float* w_t  = sm;                 // [H_][WPAD] k-major W_hh slice
    float* hT   = sm + H_ * WPAD;     // [H_][BT]   k-major h tile (warp w owns rows 64w..64w+63)
    float* part = hT + H_ * BT;       // [8][BT*NS] per-warp partials

    const int tid = threadIdx.x;
    const int g = blockIdx.x >> 3;
    const int s = blockIdx.x & 7;
    const int n0 = s * NS;
    const int b0 = g * BT;

    for (int i = tid; i < NS * H_; i += 256) {
        int n = i >> 9;
        int k = i & (H_ - 1);
        w_t[k * WPAD + n] = w_hh[(size_t)(n0 + n) * H_ + k];
    }

    const int wid = tid >> 5, lane = tid & 31;
    const int bg = lane >> 3;
    const int ng = lane & 7;
    const int k0 = wid * 64;          // this warp's k-chunk == slice `wid` of h

    // reduce-phase output mapping (and xp prefetch address), per thread
    const int o  = tid * 4;
    const int ob = o >> 6;            // batch row within group
    const int on = o & (NS - 1);      // col within slice
    const size_t obase = ((size_t)b0 + ob) * H_ + n0 + on;

    const unsigned int* myflag = &g_flag[g * NSL + wid];
    unsigned int* relflag = &g_flag[g * NSL + s];

    __syncthreads();

    for (int t = 0; t < T_; t++) {
        // prefetch xp[t] for the reduce phase (hides DRAM latency behind spin+compute)
        const float4 xv = __ldcs((const float4*)&g_xp[(size_t)t * B_ * H_ + obase]);

        // --- per-warp acquire + hT chunk load ---
        if (t > 0) {
            unsigned int v;
            do {
                asm volatile("ld.acquire.gpu.global.b32 %0, [%1];" : "=r"(v) : "l"(myflag));
            } while (v < (unsigned int)t);
            const float* hsrc = g_hs + ((size_t)(t - 1) * B_ + b0) * H_ + k0;
#pragma unroll
            for (int j = 0; j < 8; j++) {
                int idx = lane + (j << 5);        // 0..255
                int b = idx >> 4;                 // 0..15
                int q = idx & 15;                 // float4 within 64-float chunk
                float4 v4 = __ldcg((const float4*)(hsrc + (size_t)b * H_ + q * 4));
                int k = k0 + q * 4;
                hT[(k + 0) * BT + b] = v4.x;
                hT[(k + 1) * BT + b] = v4.y;
                hT[(k + 2) * BT + b] = v4.z;
                hT[(k + 3) * BT + b] = v4.w;
            }
        } else {
            for (int j = 0; j < 32; j++) hT[k0 * BT + lane + (j << 5)] = 0.0f;
        }
        __syncwarp();

        // --- compute this warp's partial c[16][64] over its k-chunk ---
        unsigned long long acc[4][4];
#pragma unroll
        for (int b = 0; b < 4; b++)
#pragma unroll
            for (int j = 0; j < 4; j++) acc[b][j] = 0ull;

#pragma unroll 4
        for (int kk = 0; kk < 64; kk++) {
            int k = k0 + kk;
            float4 hv = *(const float4*)&hT[k * BT + bg * 4];
            ulonglong2 w0 = *(const ulonglong2*)&w_t[k * WPAD + ng * 8];
            ulonglong2 w1 = *(const ulonglong2*)&w_t[k * WPAD + ng * 8 + 4];
            float hh[4] = {hv.x, hv.y, hv.z, hv.w};
            unsigned long long wv[4] = {w0.x, w0.y, w1.x, w1.y};
#pragma unroll
            for (int b = 0; b < 4; b++) {
                unsigned long long hs2 = f32x2_splat(hh[b]);
#pragma unroll
                for (int j = 0; j < 4; j++)
                    acc[b][j] = f32x2_fma(hs2, wv[j], acc[b][j]);
            }
        }

        // --- write warp partials ---
        {
            float* pw = part + wid * (BT * NS);
#pragma unroll
            for (int b = 0; b < 4; b++) {
                int r = (bg * 4 + b) * NS + ng * 8;
                ulonglong2 q0; q0.x = acc[b][0]; q0.y = acc[b][1];
                ulonglong2 q1; q1.x = acc[b][2]; q1.y = acc[b][3];
                *(ulonglong2*)&pw[r]     = q0;
                *(ulonglong2*)&pw[r + 4] = q1;
            }
        }
        __syncthreads();

        // --- reduce 8 warps, add xp, tanh, store h_t slice ---
        {
            float4 sum = *(const float4*)&part[o];
#pragma unroll
            for (int ww = 1; ww < 8; ww++) {
                float4 p = *(const float4*)&part[ww * (BT * NS) + o];
                sum.x += p.x; sum.y += p.y; sum.z += p.z; sum.w += p.w;
            }
            float4 r;
            r.x = tanhf(sum.x + xv.x);
            r.y = tanhf(sum.y + xv.y);
            r.z = tanhf(sum.z + xv.z);
            r.w = tanhf(sum.w + xv.w);
            *(float4*)&g_hs[(size_t)t * B_ * H_ + obase] = r;
        }
        __syncthreads();

        // --- release: publish slice s of step t ---
        if (tid == 0) {
            unsigned int nv = (unsigned int)(t + 1);
            asm volatile("st.release.gpu.global.b32 [%0], %1;" :: "l"(relflag), "r"(nv) : "memory");
        }
    }
}

// ---------------- launch ----------------
extern "C" void kernel_launch(void* const* d_in, const int* in_sizes, int n_in,
                              void* d_out, int out_size)
{
    const float* x    = (const float*)d_in[0];
    const float* w_ih = (const float*)d_in[1];
    const float* w_hh = (const float*)d_in[2];
    const float* b_ih = (const float*)d_in[3];
    const float* b_hh = (const float*)d_in[4];
    const float* w_fc = (const float*)d_in[5];
    const float* b_fc = (const float*)d_in[6];
    float* out = (float*)d_out;

    float* xp = nullptr;
    float* hs = nullptr;
    cudaGetSymbolAddress((void**)&xp, g_xp);
    cudaGetSymbolAddress((void**)&hs, g_hs);

    const int rec_smem = (H_ * WPAD + H_ * BT + 8 * BT * NS) * (int)sizeof(float); // 204800
    cudaFuncSetAttribute(rnn_rec_kernel, cudaFuncAttributeMaxDynamicSharedMemorySize, rec_smem);

    const int M = T_ * B_;

    zero_flag_kernel<<<1, 128>>>();

    // K1: xp = x @ w_ih^T + (b_ih + b_hh)
    sgemm_bias_kernel<<<dim3(H_ / 128, M / 128), 256>>>(x, w_ih, b_ih, b_hh, xp, M, H_, I_);

    // K2: recurrence (persistent, 128 CTAs, per-slice flag sync)
    rnn_rec_kernel<<<NG * NSL, 256, rec_smem>>>(w_hh);

    // K3: out = hs @ w_fc^T + b_fc
    sgemm_bias_kernel<<<dim3(I_ / 128, M / 128), 256>>>(hs, w_fc, b_fc, nullptr, out, M, I_, H_);
}

// round 7
// speedup vs baseline: 1.6613x; 1.1051x over previous
#include <cuda_runtime.h>
#include <cuda_bf16.h>
#include <cstdint>

// RNNModel: T=512, B=256, I=256, H=512, fp32.
//   K1: xp = x @ w_ih^T + (b_ih + b_hh)      -> mma.sync m16n8k8 TF32 (3xTF32) GEMM
//   K2: h_t = tanh(xp_t + h_{t-1} @ w_hh^T)  -> R1 persistent kernel (group counter; best measured)
//   K3: out = hs @ w_fc^T + b_fc             -> mma.sync 3xTF32 GEMM
// tcgen05 unavailable (ptxas target compute_103); legacy mma.sync IS available.

#define T_ 512
#define B_ 256
#define I_ 256
#define H_ 512

#define NG  16
#define NSL 8
#define BT  16
#define NS  64
#define WPAD 68

__device__ float g_xp[(size_t)T_ * B_ * H_];
__device__ float g_hs[(size_t)T_ * B_ * H_];
__device__ int   g_cnt[NG];

// ---------------- f32x2 helpers (K2) ----------------
__device__ __forceinline__ unsigned long long f32x2_fma(unsigned long long a,
                                                        unsigned long long b,
                                                        unsigned long long c) {
    unsigned long long d;
    asm("fma.rn.f32x2 %0, %1, %2, %3;" : "=l"(d) : "l"(a), "l"(b), "l"(c));
    return d;
}
__device__ __forceinline__ unsigned long long f32x2_splat(float x) {
    unsigned long long d;
    unsigned int xi = __float_as_uint(x);
    asm("mov.b64 %0, {%1, %1};" : "=l"(d) : "r"(xi));
    return d;
}

// ---------------- tf32 helpers ----------------
__device__ __forceinline__ uint32_t cvt_tf32(float x) {
    uint32_t r;
    asm("cvt.rna.tf32.f32 %0, %1;" : "=r"(r) : "f"(x));
    return r;
}
__device__ __forceinline__ void split_tf32(float x, float& big, float& small) {
    big = __uint_as_float(cvt_tf32(x));
    small = __uint_as_float(cvt_tf32(x - big));
}
__device__ __forceinline__ void mma16n8k8(float* c, const uint32_t* a, const uint32_t* b) {
    asm volatile("mma.sync.aligned.m16n8k8.row.col.f32.tf32.tf32.f32 "
        "{%0,%1,%2,%3}, {%4,%5,%6,%7}, {%8,%9}, {%0,%1,%2,%3};"
        : "+f"(c[0]), "+f"(c[1]), "+f"(c[2]), "+f"(c[3])
        : "r"(a[0]), "r"(a[1]), "r"(a[2]), "r"(a[3]), "r"(b[0]), "r"(b[1]));
}

// ---------------- K1/K3: 3xTF32 mma.sync GEMM ----------------
// C[M,N] = A[M,K]*B[N,K]^T + b1[n] (+b2[n]).
// CTA 128x128, 8 warps (4m x 2n, warp tile 32x64), K-chunk 16, double-buffered.
// Smem arrays padded to stride 20 floats: (8row x 4col) frag loads are bank-conflict-free.
#define KCHUNK 16
#define PADS 20
#define ARRF (128 * PADS)       // floats per array
#define STGF (4 * ARRF)         // AB, AS, BB, BS
#define GEMM_SMEM_BYTES (2 * STGF * 4)   // 81920

__global__ void __launch_bounds__(256) mma_gemm_kernel(
    const float* __restrict__ A, const float* __restrict__ Bm,
    const float* __restrict__ b1, const float* __restrict__ b2,
    float* __restrict__ C, int M, int N, int K)
{
    extern __shared__ float sh[];
    const int tid = threadIdx.x;
    const int m0 = blockIdx.y << 7;
    const int n0 = blockIdx.x << 7;
    const int lane = tid & 31, wid = tid >> 5;
    const int gid = lane >> 2, tig = lane & 3;
    const int wm = wid >> 1, wn = wid & 1;

    // loader mapping: thread covers row tid>>1, k-offset (tid&1)*8 (two float4)
    const int lrow = tid >> 1;
    const int lko  = (tid & 1) << 3;

    const float* Ap = A + (size_t)(m0 + lrow) * K + lko;
    const float* Bp = Bm + (size_t)(n0 + lrow) * K + lko;

    float acc[2][8][4];
#pragma unroll
    for (int mt = 0; mt < 2; mt++)
#pragma unroll
        for (int nt = 0; nt < 8; nt++)
#pragma unroll
            for (int i = 0; i < 4; i++) acc[mt][nt][i] = 0.0f;

    const int NC = K >> 4;

    // raw prefetch regs for current chunk
    float4 ar0 = *(const float4*)(Ap);
    float4 ar1 = *(const float4*)(Ap + 4);
    float4 br0 = *(const float4*)(Bp);
    float4 br1 = *(const float4*)(Bp + 4);

    for (int kc = 0; kc < NC; kc++) {
        const int s = kc & 1;
        float* AB = sh + s * STGF;
        float* AS = AB + ARRF;
        float* BB = AS + ARRF;
        float* BS = BB + ARRF;

        // split + STS current chunk
        {
            float4 bg, sm;
            const int sa = lrow * PADS + lko;
            split_tf32(ar0.x, bg.x, sm.x); split_tf32(ar0.y, bg.y, sm.y);
            split_tf32(ar0.z, bg.z, sm.z); split_tf32(ar0.w, bg.w, sm.w);
            *(float4*)(AB + sa) = bg; *(float4*)(AS + sa) = sm;
            split_tf32(ar1.x, bg.x, sm.x); split_tf32(ar1.y, bg.y, sm.y);
            split_tf32(ar1.z, bg.z, sm.z); split_tf32(ar1.w, bg.w, sm.w);
            *(float4*)(AB + sa + 4) = bg; *(float4*)(AS + sa + 4) = sm;
            split_tf32(br0.x, bg.x, sm.x); split_tf32(br0.y, bg.y, sm.y);
            split_tf32(br0.z, bg.z, sm.z); split_tf32(br0.w, bg.w, sm.w);
            *(float4*)(BB + sa) = bg; *(float4*)(BS + sa) = sm;
            split_tf32(br1.x, bg.x, sm.x); split_tf32(br1.y, bg.y, sm.y);
            split_tf32(br1.z, bg.z, sm.z); split_tf32(br1.w, bg.w, sm.w);
            *(float4*)(BB + sa + 4) = bg; *(float4*)(BS + sa + 4) = sm;
        }
        __syncthreads();

        // prefetch next chunk raw (overlaps compute below)
        if (kc + 1 < NC) {
            const int K0 = (kc + 1) << 4;
            ar0 = *(const float4*)(Ap + K0);
            ar1 = *(const float4*)(Ap + K0 + 4);
            br0 = *(const float4*)(Bp + K0);
            br1 = *(const float4*)(Bp + K0 + 4);
        }

        // compute two k8 sub-steps
#pragma unroll
        for (int lk8 = 0; lk8 < KCHUNK; lk8 += 8) {
            uint32_t ab[2][4], as_[2][4], bb[8][2], bs[8][2];
#pragma unroll
            for (int mt = 0; mt < 2; mt++) {
                const int r = (wm << 5) + (mt << 4) + gid;
                ab[mt][0]  = __float_as_uint(AB[r * PADS + lk8 + tig]);
                ab[mt][1]  = __float_as_uint(AB[(r + 8) * PADS + lk8 + tig]);
                ab[mt][2]  = __float_as_uint(AB[r * PADS + lk8 + tig + 4]);
                ab[mt][3]  = __float_as_uint(AB[(r + 8) * PADS + lk8 + tig + 4]);
                as_[mt][0] = __float_as_uint(AS[r * PADS + lk8 + tig]);
                as_[mt][1] = __float_as_uint(AS[(r + 8) * PADS + lk8 + tig]);
                as_[mt][2] = __float_as_uint(AS[r * PADS + lk8 + tig + 4]);
                as_[mt][3] = __float_as_uint(AS[(r + 8) * PADS + lk8 + tig + 4]);
            }
#pragma unroll
            for (int nt = 0; nt < 8; nt++) {
                const int nn = (wn << 6) + (nt << 3) + gid;
                bb[nt][0] = __float_as_uint(BB[nn * PADS + lk8 + tig]);
                bb[nt][1] = __float_as_uint(BB[nn * PADS + lk8 + tig + 4]);
                bs[nt][0] = __float_as_uint(BS[nn * PADS + lk8 + tig]);
                bs[nt][1] = __float_as_uint(BS[nn * PADS + lk8 + tig + 4]);
            }
#pragma unroll
            for (int mt = 0; mt < 2; mt++)
#pragma unroll
                for (int nt = 0; nt < 8; nt++) {
                    mma16n8k8(acc[mt][nt], ab[mt], bb[nt]);
                    mma16n8k8(acc[mt][nt], as_[mt], bb[nt]);
                    mma16n8k8(acc[mt][nt], ab[mt], bs[nt]);
                }
        }
        __syncthreads();
    }

    // epilogue: c{0,1}=(gid, 2tig+0/1), c{2,3}=(gid+8, 2tig+0/1)
    float bias[8][2];
#pragma unroll
    for (int nt = 0; nt < 8; nt++) {
        const int col = n0 + (wn << 6) + (nt << 3) + (tig << 1);
        float v0 = b1[col], v1 = b1[col + 1];
        if (b2) { v0 += b2[col]; v1 += b2[col + 1]; }
        bias[nt][0] = v0; bias[nt][1] = v1;
    }
#pragma unroll
    for (int mt = 0; mt < 2; mt++)
#pragma unroll
        for (int half = 0; half < 2; half++) {
            const int row = m0 + (wm << 5) + (mt << 4) + gid + (half << 3);
            float* crow = C + (size_t)row * N;
#pragma unroll
            for (int nt = 0; nt < 8; nt++) {
                const int col = n0 + (wn << 6) + (nt << 3) + (tig << 1);
                float2 v;
                v.x = acc[mt][nt][half * 2 + 0] + bias[nt][0];
                v.y = acc[mt][nt][half * 2 + 1] + bias[nt][1];
                *(float2*)(crow + col) = v;
            }
        }
}

// ---------------- init ----------------
__global__ void zero_cnt_kernel() {
    if (threadIdx.x < NG) g_cnt[threadIdx.x] = 0;
}

// ---------------- K2: persistent recurrence (R1 verbatim — best measured) ----------------
__global__ void __launch_bounds__(256) rnn_rec_kernel(const float* __restrict__ w_hh)
{
    extern __shared__ float sm[];
    float* w_t  = sm;
    float* hT   = sm + H_ * WPAD;
    float* part = hT + H_ * BT;

    const int tid = threadIdx.x;
    const int g = blockIdx.x >> 3;
    const int s = blockIdx.x & 7;
    const int n0 = s * NS;
    const int b0 = g * BT;

    for (int i = tid; i < NS * H_; i += 256) {
        int n = i >> 9;
        int k = i & (H_ - 1);
        w_t[k * WPAD + n] = w_hh[(size_t)(n0 + n) * H_ + k];
    }

    const int wid = tid >> 5, lane = tid & 31;
    const int bg = lane >> 3;
    const int ng = lane & 7;
    const int k0 = wid * 64;

    __syncthreads();

    for (int t = 0; t < T_; t++) {
        if (t > 0) {
            if (tid == 0) {
                volatile int* c = g_cnt + g;
                while (*c < NSL * t) __nanosleep(40);
                __threadfence();
            }
            __syncthreads();
            const float* hsrc = g_hs + ((size_t)(t - 1) * B_ + b0) * H_;
            for (int i = tid; i < BT * H_; i += 256) {
                int b = i >> 9;
                int k = i & (H_ - 1);
                hT[k * BT + b] = hsrc[i];
            }
        } else {
            for (int i = tid; i < BT * H_; i += 256) hT[i] = 0.0f;
        }
        __syncthreads();

        unsigned long long acc[4][4];
#pragma unroll
        for (int b = 0; b < 4; b++)
#pragma unroll
            for (int j = 0; j < 4; j++) acc[b][j] = 0ull;

#pragma unroll 4
        for (int kk = 0; kk < 64; kk++) {
            int k = k0 + kk;
            float4 hv = *(const float4*)&hT[k * BT + bg * 4];
            ulonglong2 w0 = *(const ulonglong2*)&w_t[k * WPAD + ng * 8];
            ulonglong2 w1 = *(const ulonglong2*)&w_t[k * WPAD + ng * 8 + 4];
            float hh[4] = {hv.x, hv.y, hv.z, hv.w};
            unsigned long long wv[4] = {w0.x, w0.y, w1.x, w1.y};
#pragma unroll
            for (int b = 0; b < 4; b++) {
                unsigned long long hs2 = f32x2_splat(hh[b]);
#pragma unroll
                for (int j = 0; j < 4; j++)
                    acc[b][j] = f32x2_fma(hs2, wv[j], acc[b][j]);
            }
        }

        {
            float* pw = part + wid * (BT * NS);
#pragma unroll
            for (int b = 0; b < 4; b++) {
                int r = (bg * 4 + b) * NS + ng * 8;
                ulonglong2 q0; q0.x = acc[b][0]; q0.y = acc[b][1];
                ulonglong2 q1; q1.x = acc[b][2]; q1.y = acc[b][3];
                *(ulonglong2*)&pw[r]     = q0;
                *(ulonglong2*)&pw[r + 4] = q1;
            }
        }
        __syncthreads();

        {
            int o = tid * 4;
            float4 sum = *(const float4*)&part[o];
#pragma unroll
            for (int ww = 1; ww < 8; ww++) {
                float4 p = *(const float4*)&part[ww * (BT * NS) + o];
                sum.x += p.x; sum.y += p.y; sum.z += p.z; sum.w += p.w;
            }
            int b = o >> 6;
            int n = o & (NS - 1);
            size_t gidx = ((size_t)t * B_ + b0 + b) * H_ + n0 + n;
            float4 xv = *(const float4*)&g_xp[gidx];
            float4 r;
            r.x = tanhf(sum.x + xv.x);
            r.y = tanhf(sum.y + xv.y);
            r.z = tanhf(sum.z + xv.z);
            r.w = tanhf(sum.w + xv.w);
            *(float4*)&g_hs[gidx] = r;
        }
        __syncthreads();

        if (tid == 0) {
            __threadfence();
            atomicAdd(&g_cnt[g], 1);
        }
    }
}

// ---------------- launch ----------------
extern "C" void kernel_launch(void* const* d_in, const int* in_sizes, int n_in,
                              void* d_out, int out_size)
{
    const float* x    = (const float*)d_in[0];
    const float* w_ih = (const float*)d_in[1];
    const float* w_hh = (const float*)d_in[2];
    const float* b_ih = (const float*)d_in[3];
    const float* b_hh = (const float*)d_in[4];
    const float* w_fc = (const float*)d_in[5];
    const float* b_fc = (const float*)d_in[6];
    float* out = (float*)d_out;

    float* xp = nullptr;
    float* hs = nullptr;
    cudaGetSymbolAddress((void**)&xp, g_xp);
    cudaGetSymbolAddress((void**)&hs, g_hs);

    const int rec_smem = (H_ * WPAD + H_ * BT + 8 * BT * NS) * (int)sizeof(float); // 204800
    cudaFuncSetAttribute(rnn_rec_kernel, cudaFuncAttributeMaxDynamicSharedMemorySize, rec_smem);
    cudaFuncSetAttribute(mma_gemm_kernel, cudaFuncAttributeMaxDynamicSharedMemorySize, GEMM_SMEM_BYTES);

    const int M = T_ * B_;

    zero_cnt_kernel<<<1, 32>>>();

    // K1: xp = x @ w_ih^T + (b_ih + b_hh)   (M=131072, N=512, K=256)
    mma_gemm_kernel<<<dim3(H_ / 128, M / 128), 256, GEMM_SMEM_BYTES>>>(x, w_ih, b_ih, b_hh, xp, M, H_, I_);

    // K2: recurrence (persistent, 128 CTAs)
    rnn_rec_kernel<<<NG * NSL, 256, rec_smem>>>(w_hh);

    // K3: out = hs @ w_fc^T + b_fc          (M=131072, N=256, K=512)
    mma_gemm_kernel<<<dim3(I_ / 128, M / 128), 256, GEMM_SMEM_BYTES>>>(hs, w_fc, b_fc, nullptr, out, M, I_, H_);
}

// round 8
// speedup vs baseline: 1.9544x; 1.1764x over previous
#include <cuda_runtime.h>
#include <cuda_bf16.h>
#include <cstdint>

// RNNModel: T=512, B=256, I=256, H=512, fp32.
//   K1: xp = x @ w_ih^T + (b_ih + b_hh)      -> mma.sync 3xTF32 GEMM (2 CTA/SM)
//   K2: h_t = tanh(xp_t + h_{t-1} @ w_hh^T)  -> persistent; warps split N (no reduce), b-major hT
//   K3: out = hs @ w_fc^T + b_fc             -> mma.sync 3xTF32 GEMM

#define T_ 512
#define B_ 256
#define I_ 256
#define H_ 512

#define NG  16
#define NSL 8
#define BT  16
#define NS  64
#define WPAD 68
#define HSTR 516   // b-major hT row stride (floats); 516*4 % 16 == 0, bank-spread

__device__ float g_xp[(size_t)T_ * B_ * H_];
__device__ float g_hs[(size_t)T_ * B_ * H_];
__device__ int   g_cnt[NG];

// ---------------- helpers ----------------
__device__ __forceinline__ unsigned long long f32x2_fma(unsigned long long a,
                                                        unsigned long long b,
                                                        unsigned long long c) {
    unsigned long long d;
    asm("fma.rn.f32x2 %0, %1, %2, %3;" : "=l"(d) : "l"(a), "l"(b), "l"(c));
    return d;
}
__device__ __forceinline__ unsigned long long f32x2_splat(float x) {
    unsigned long long d;
    unsigned int xi = __float_as_uint(x);
    asm("mov.b64 %0, {%1, %1};" : "=l"(d) : "r"(xi));
    return d;
}
__device__ __forceinline__ float2 f32x2_unpack(unsigned long long v) {
    unsigned int lo, hi;
    asm("mov.b64 {%0, %1}, %2;" : "=r"(lo), "=r"(hi) : "l"(v));
    float2 r;
    r.x = __uint_as_float(lo);
    r.y = __uint_as_float(hi);
    return r;
}
__device__ __forceinline__ uint32_t smem_u32(const void* p) {
    uint32_t a;
    asm("{ .reg .u64 t; cvta.to.shared.u64 t, %1; cvt.u32.u64 %0, t; }" : "=r"(a) : "l"(p));
    return a;
}
__device__ __forceinline__ void cp_async16(uint32_t saddr, const void* gptr) {
    asm volatile("cp.async.ca.shared.global [%0], [%1], 16;" :: "r"(saddr), "l"(gptr));
}
#define CP_COMMIT_WAIT() \
    asm volatile("cp.async.commit_group;\n\tcp.async.wait_group 0;" ::: "memory")

// ---------------- tf32 helpers ----------------
__device__ __forceinline__ uint32_t cvt_tf32(float x) {
    uint32_t r;
    asm("cvt.rna.tf32.f32 %0, %1;" : "=r"(r) : "f"(x));
    return r;
}
__device__ __forceinline__ void split_tf32(float x, float& big, float& small) {
    big = __uint_as_float(cvt_tf32(x));
    small = __uint_as_float(cvt_tf32(x - big));
}
__device__ __forceinline__ void mma16n8k8(float* c, const uint32_t* a, const uint32_t* b) {
    asm volatile("mma.sync.aligned.m16n8k8.row.col.f32.tf32.tf32.f32 "
        "{%0,%1,%2,%3}, {%4,%5,%6,%7}, {%8,%9}, {%0,%1,%2,%3};"
        : "+f"(c[0]), "+f"(c[1]), "+f"(c[2]), "+f"(c[3])
        : "r"(a[0]), "r"(a[1]), "r"(a[2]), "r"(a[3]), "r"(b[0]), "r"(b[1]));
}

// ---------------- K1/K3: 3xTF32 mma.sync GEMM (now 2 CTA/SM) ----------------
#define KCHUNK 16
#define PADS 20
#define ARRF (128 * PADS)
#define STGF (4 * ARRF)
#define GEMM_SMEM_BYTES (2 * STGF * 4)   // 81920

__global__ void __launch_bounds__(256, 2) mma_gemm_kernel(
    const float* __restrict__ A, const float* __restrict__ Bm,
    const float* __restrict__ b1, const float* __restrict__ b2,
    float* __restrict__ C, int M, int N, int K)
{
    extern __shared__ float sh[];
    const int tid = threadIdx.x;
    const int m0 = blockIdx.y << 7;
    const int n0 = blockIdx.x << 7;
    const int lane = tid & 31, wid = tid >> 5;
    const int gid = lane >> 2, tig = lane & 3;
    const int wm = wid >> 1, wn = wid & 1;

    const int lrow = tid >> 1;
    const int lko  = (tid & 1) << 3;

    const float* Ap = A + (size_t)(m0 + lrow) * K + lko;
    const float* Bp = Bm + (size_t)(n0 + lrow) * K + lko;

    float acc[2][8][4];
#pragma unroll
    for (int mt = 0; mt < 2; mt++)
#pragma unroll
        for (int nt = 0; nt < 8; nt++)
#pragma unroll
            for (int i = 0; i < 4; i++) acc[mt][nt][i] = 0.0f;

    const int NC = K >> 4;

    float4 ar0 = *(const float4*)(Ap);
    float4 ar1 = *(const float4*)(Ap + 4);
    float4 br0 = *(const float4*)(Bp);
    float4 br1 = *(const float4*)(Bp + 4);

    for (int kc = 0; kc < NC; kc++) {
        const int s = kc & 1;
        float* AB = sh + s * STGF;
        float* AS = AB + ARRF;
        float* BB = AS + ARRF;
        float* BS = BB + ARRF;

        {
            float4 bg, sm;
            const int sa = lrow * PADS + lko;
            split_tf32(ar0.x, bg.x, sm.x); split_tf32(ar0.y, bg.y, sm.y);
            split_tf32(ar0.z, bg.z, sm.z); split_tf32(ar0.w, bg.w, sm.w);
            *(float4*)(AB + sa) = bg; *(float4*)(AS + sa) = sm;
            split_tf32(ar1.x, bg.x, sm.x); split_tf32(ar1.y, bg.y, sm.y);
            split_tf32(ar1.z, bg.z, sm.z); split_tf32(ar1.w, bg.w, sm.w);
            *(float4*)(AB + sa + 4) = bg; *(float4*)(AS + sa + 4) = sm;
            split_tf32(br0.x, bg.x, sm.x); split_tf32(br0.y, bg.y, sm.y);
            split_tf32(br0.z, bg.z, sm.z); split_tf32(br0.w, bg.w, sm.w);
            *(float4*)(BB + sa) = bg; *(float4*)(BS + sa) = sm;
            split_tf32(br1.x, bg.x, sm.x); split_tf32(br1.y, bg.y, sm.y);
            split_tf32(br1.z, bg.z, sm.z); split_tf32(br1.w, bg.w, sm.w);
            *(float4*)(BB + sa + 4) = bg; *(float4*)(BS + sa + 4) = sm;
        }
        __syncthreads();

        if (kc + 1 < NC) {
            const int K0 = (kc + 1) << 4;
            ar0 = *(const float4*)(Ap + K0);
            ar1 = *(const float4*)(Ap + K0 + 4);
            br0 = *(const float4*)(Bp + K0);
            br1 = *(const float4*)(Bp + K0 + 4);
        }

#pragma unroll
        for (int lk8 = 0; lk8 < KCHUNK; lk8 += 8) {
            uint32_t ab[2][4], as_[2][4], bb[8][2], bs[8][2];
#pragma unroll
            for (int mt = 0; mt < 2; mt++) {
                const int r = (wm << 5) + (mt << 4) + gid;
                ab[mt][0]  = __float_as_uint(AB[r * PADS + lk8 + tig]);
                ab[mt][1]  = __float_as_uint(AB[(r + 8) * PADS + lk8 + tig]);
                ab[mt][2]  = __float_as_uint(AB[r * PADS + lk8 + tig + 4]);
                ab[mt][3]  = __float_as_uint(AB[(r + 8) * PADS + lk8 + tig + 4]);
                as_[mt][0] = __float_as_uint(AS[r * PADS + lk8 + tig]);
                as_[mt][1] = __float_as_uint(AS[(r + 8) * PADS + lk8 + tig]);
                as_[mt][2] = __float_as_uint(AS[r * PADS + lk8 + tig + 4]);
                as_[mt][3] = __float_as_uint(AS[(r + 8) * PADS + lk8 + tig + 4]);
            }
#pragma unroll
            for (int nt = 0; nt < 8; nt++) {
                const int nn = (wn << 6) + (nt << 3) + gid;
                bb[nt][0] = __float_as_uint(BB[nn * PADS + lk8 + tig]);
                bb[nt][1] = __float_as_uint(BB[nn * PADS + lk8 + tig + 4]);
                bs[nt][0] = __float_as_uint(BS[nn * PADS + lk8 + tig]);
                bs[nt][1] = __float_as_uint(BS[nn * PADS + lk8 + tig + 4]);
            }
#pragma unroll
            for (int mt = 0; mt < 2; mt++)
#pragma unroll
                for (int nt = 0; nt < 8; nt++) {
                    mma16n8k8(acc[mt][nt], ab[mt], bb[nt]);
                    mma16n8k8(acc[mt][nt], as_[mt], bb[nt]);
                    mma16n8k8(acc[mt][nt], ab[mt], bs[nt]);
                }
        }
        __syncthreads();
    }

    float bias[8][2];
#pragma unroll
    for (int nt = 0; nt < 8; nt++) {
        const int col = n0 + (wn << 6) + (nt << 3) + (tig << 1);
        float v0 = b1[col], v1 = b1[col + 1];
        if (b2) { v0 += b2[col]; v1 += b2[col + 1]; }
        bias[nt][0] = v0; bias[nt][1] = v1;
    }
#pragma unroll
    for (int mt = 0; mt < 2; mt++)
#pragma unroll
        for (int half = 0; half < 2; half++) {
            const int row = m0 + (wm << 5) + (mt << 4) + gid + (half << 3);
            float* crow = C + (size_t)row * N;
#pragma unroll
            for (int nt = 0; nt < 8; nt++) {
                const int col = n0 + (wn << 6) + (nt << 3) + (tig << 1);
                float2 v;
                v.x = acc[mt][nt][half * 2 + 0] + bias[nt][0];
                v.y = acc[mt][nt][half * 2 + 1] + bias[nt][1];
                *(float2*)(crow + col) = v;
            }
        }
}

// ---------------- init ----------------
__global__ void zero_cnt_kernel() {
    if (threadIdx.x < NG) g_cnt[threadIdx.x] = 0;
}

// ---------------- K2: persistent recurrence, N-split warps ----------------
// 128 CTAs = 16 groups x 8 slices, 1/SM (smem 172KB). Warp w owns output cols
// [w*8, w*8+8) over FULL K=512 -> final accumulators in registers, no reduction.
// hT is b-major: staging is a straight 32KB cp.async memcpy (conflict-free);
// compute reads h as broadcast float4 and W as 2-address broadcast ulonglong2.
__global__ void __launch_bounds__(256) rnn_rec_kernel(const float* __restrict__ w_hh)
{
    extern __shared__ float sm[];
    float* w_t = sm;                 // [512][WPAD] k-major W slice
    float* hT  = sm + H_ * WPAD;     // [BT][HSTR]  b-major h tile

    const int tid = threadIdx.x;
    const int g = blockIdx.x >> 3;
    const int s = blockIdx.x & 7;
    const int n0 = s * NS;
    const int b0 = g * BT;

    // cache W_hh slice: w_t[k][n] = w_hh[n0+n][k]
    for (int i = tid; i < NS * H_; i += 256) {
        int n = i >> 9;
        int k = i & (H_ - 1);
        w_t[k * WPAD + n] = w_hh[(size_t)(n0 + n) * H_ + k];
    }

    const int wid = tid >> 5, lane = tid & 31;
    const int b  = lane >> 1;        // batch row (0..15)
    const int nh = lane & 1;         // col half (0/1)
    const int c0 = wid * 8 + nh * 4; // 4 output cols

    const size_t obase = ((size_t)(b0 + b)) * H_ + n0 + c0;
    const uint32_t hT_u32 = smem_u32(hT);

    __syncthreads();

    for (int t = 0; t < T_; t++) {
        // prefetch xp[t] (independent of the flag)
        const float4 xv = __ldcs((const float4*)&g_xp[(size_t)t * B_ * H_ + obase]);

        // --- acquire h_{t-1} ---
        if (t > 0) {
            if (tid == 0) {
                volatile int* c = g_cnt + g;
                while (*c < NSL * t) __nanosleep(40);
                __threadfence();
            }
            __syncthreads();
            const float* hsrc = g_hs + ((size_t)(t - 1) * B_ + b0) * H_;
#pragma unroll
            for (int j = 0; j < 8; j++) {
                int i4 = tid + (j << 8);          // float4 index 0..2047
                int bb = i4 >> 7;                 // batch row
                int k4 = i4 & 127;                // float4 within row
                cp_async16(hT_u32 + (uint32_t)(bb * HSTR + k4 * 4) * 4,
                           hsrc + (size_t)i4 * 4);
            }
            CP_COMMIT_WAIT();
        } else {
            for (int i = tid; i < BT * HSTR; i += 256) hT[i] = 0.0f;
        }
        __syncthreads();

        // --- compute 4 output cols for batch row b over full K ---
        unsigned long long a0 = 0ull, a1 = 0ull;
        const float* hrow = hT + b * HSTR;
        const float* wcol = w_t + c0;
#pragma unroll 4
        for (int k4 = 0; k4 < 128; k4++) {
            const float4 hv = *(const float4*)(hrow + (k4 << 2));
            const float hh[4] = {hv.x, hv.y, hv.z, hv.w};
#pragma unroll
            for (int c = 0; c < 4; c++) {
                const ulonglong2 wv = *(const ulonglong2*)(wcol + ((k4 << 2) + c) * WPAD);
                const unsigned long long hs2 = f32x2_splat(hh[c]);
                a0 = f32x2_fma(hs2, wv.x, a0);
                a1 = f32x2_fma(hs2, wv.y, a1);
            }
        }

        // --- epilogue: add xp, tanh, store h_t (no cross-warp reduce needed) ---
        {
            const float2 lo = f32x2_unpack(a0);
            const float2 hi = f32x2_unpack(a1);
            float4 r;
            r.x = tanhf(lo.x + xv.x);
            r.y = tanhf(lo.y + xv.y);
            r.z = tanhf(hi.x + xv.z);
            r.w = tanhf(hi.y + xv.w);
            *(float4*)&g_hs[(size_t)t * B_ * H_ + obase] = r;
        }
        __syncthreads();

        // --- release slice s of step t ---
        if (tid == 0) {
            __threadfence();
            atomicAdd(&g_cnt[g], 1);
        }
    }
}

// ---------------- launch ----------------
extern "C" void kernel_launch(void* const* d_in, const int* in_sizes, int n_in,
                              void* d_out, int out_size)
{
    const float* x    = (const float*)d_in[0];
    const float* w_ih = (const float*)d_in[1];
    const float* w_hh = (const float*)d_in[2];
    const float* b_ih = (const float*)d_in[3];
    const float* b_hh = (const float*)d_in[4];
    const float* w_fc = (const float*)d_in[5];
    const float* b_fc = (const float*)d_in[6];
    float* out = (float*)d_out;

    float* xp = nullptr;
    float* hs = nullptr;
    cudaGetSymbolAddress((void**)&xp, g_xp);
    cudaGetSymbolAddress((void**)&hs, g_hs);

    const int rec_smem = (H_ * WPAD + BT * HSTR) * (int)sizeof(float); // 172288
    cudaFuncSetAttribute(rnn_rec_kernel, cudaFuncAttributeMaxDynamicSharedMemorySize, rec_smem);
    cudaFuncSetAttribute(mma_gemm_kernel, cudaFuncAttributeMaxDynamicSharedMemorySize, GEMM_SMEM_BYTES);

    const int M = T_ * B_;

    zero_cnt_kernel<<<1, 32>>>();

    // K1: xp = x @ w_ih^T + (b_ih + b_hh)
    mma_gemm_kernel<<<dim3(H_ / 128, M / 128), 256, GEMM_SMEM_BYTES>>>(x, w_ih, b_ih, b_hh, xp, M, H_, I_);

    // K2: recurrence (persistent, 128 CTAs)
    rnn_rec_kernel<<<NG * NSL, 256, rec_smem>>>(w_hh);

    // K3: out = hs @ w_fc^T + b_fc
    mma_gemm_kernel<<<dim3(I_ / 128, M / 128), 256, GEMM_SMEM_BYTES>>>(hs, w_fc, b_fc, nullptr, out, M, I_, H_);
}